// round 5
// baseline (speedup 1.0000x reference)
#include <cuda_runtime.h>
#include <cuda_fp16.h>
#include <math.h>

#define NN 100000
#define EE 1600000
#define HH 128
#define GG 256
#define CC 5
#define SCAN_CHUNK 1024
#define NBLK ((NN + SCAN_CHUNK - 1) / SCAN_CHUNK)   // 98
#define LDI 136   // smem A-tile stride in halves
#define LDW 136   // smem W-tile stride in halves

// -------- device scratch (static, allocation-free) --------
__device__ __align__(16) __half g_hA[NN * HH];
__device__ __align__(16) __half g_hB[NN * HH];
__device__ __align__(16) __half g_Wt[3 * HH * HH];   // fp16, transposed [n][k]
__device__ __align__(16) float  g_xa[NN * 4];
__device__ int   g_cnt[NN];
__device__ int   g_fill[NN];
__device__ int   g_rowptr[NN + 1];
__device__ int   g_col[EE];
__device__ float g_dinv[NN];
__device__ int   g_part[NBLK];
__device__ __align__(16) float g_pooled[GG * HH];
__device__ float g_gcnt[GG];
__device__ int   g_shift;   // 0: int32 indices, 1: int64 (read low word)

__device__ __forceinline__ __half* hsel(int k) { return k ? g_hB : g_hA; }

// -------- tensor-core helpers --------
__device__ __forceinline__ void ldsm_x4(unsigned &r0, unsigned &r1, unsigned &r2, unsigned &r3,
                                        unsigned addr) {
    asm volatile("ldmatrix.sync.aligned.m8n8.x4.shared.b16 {%0,%1,%2,%3},[%4];"
                 : "=r"(r0), "=r"(r1), "=r"(r2), "=r"(r3) : "r"(addr));
}
__device__ __forceinline__ void ldsm_x2(unsigned &r0, unsigned &r1, unsigned addr) {
    asm volatile("ldmatrix.sync.aligned.m8n8.x2.shared.b16 {%0,%1},[%2];"
                 : "=r"(r0), "=r"(r1) : "r"(addr));
}
__device__ __forceinline__ void mma16816(float* c, unsigned a0, unsigned a1, unsigned a2,
                                         unsigned a3, unsigned b0, unsigned b1) {
    asm volatile("mma.sync.aligned.m16n8k16.row.col.f32.f16.f16.f32 "
                 "{%0,%1,%2,%3},{%4,%5,%6,%7},{%8,%9},{%0,%1,%2,%3};"
                 : "+f"(c[0]), "+f"(c[1]), "+f"(c[2]), "+f"(c[3])
                 : "r"(a0), "r"(a1), "r"(a2), "r"(a3), "r"(b0), "r"(b1));
}

__device__ __forceinline__ float4 h2x2_to_f4(uint2 v) {
    float2 lo = __half22float2(*(const __half2*)&v.x);
    float2 hi = __half22float2(*(const __half2*)&v.y);
    return make_float4(lo.x, lo.y, hi.x, hi.y);
}

// -------- dtype detection --------
__global__ void detect_k(const int* __restrict__ w) {
    __shared__ int sor[256];
    int t = threadIdx.x;
    int o = 0;
    #pragma unroll
    for (int k = 0; k < 16; k++) {
        int j = (t * 16 + k) * (EE / 4096);
        o |= w[2 * j + 1];
    }
    sor[t] = o;
    __syncthreads();
    for (int s = 128; s; s >>= 1) { if (t < s) sor[t] |= sor[t + s]; __syncthreads(); }
    if (t == 0) g_shift = (sor[0] == 0) ? 1 : 0;
}

// -------- zero scratch --------
__global__ void zero_k() {
    int i = blockIdx.x * blockDim.x + threadIdx.x;
    if (i < NN) { g_cnt[i] = 0; g_fill[i] = 0; }
    if (i < GG * HH) g_pooled[i] = 0.0f;
    if (i < GG) g_gcnt[i] = 0.0f;
}

// -------- weight convert: W[k][n] fp32 -> Wt[n][k] fp16 --------
__global__ void wcvt_k(const float* __restrict__ W2, const float* __restrict__ W3,
                       const float* __restrict__ W4) {
    int idx = blockIdx.x * blockDim.x + threadIdx.x;
    if (idx >= 3 * HH * HH) return;
    int sel = idx >> 14;
    int loc = idx & 16383;
    int n = loc >> 7, k = loc & 127;
    const float* s = (sel == 0) ? W2 : (sel == 1) ? W3 : W4;
    g_Wt[idx] = __float2half(s[k * HH + n]);
}

// -------- load 4 consecutive edge indices (either dtype), base%4==0 --------
__device__ __forceinline__ int4 load4idx(const int* __restrict__ w, int base, int sh) {
    if (sh == 0) {
        return *(const int4*)(w + base);
    } else {
        int4 a = *(const int4*)(w + 2 * base);
        int4 b = *(const int4*)(w + 2 * base + 4);
        return make_int4(a.x, a.z, b.x, b.z);
    }
}

// -------- degree count: 4 edges per thread --------
__global__ void count_k(const int* __restrict__ w) {
    int t4 = (blockIdx.x * blockDim.x + threadIdx.x) * 4;
    if (t4 >= EE) return;
    int sh = g_shift;
    int4 d = load4idx(w, EE + t4, sh);
    atomicAdd(&g_cnt[d.x], 1);
    atomicAdd(&g_cnt[d.y], 1);
    atomicAdd(&g_cnt[d.z], 1);
    atomicAdd(&g_cnt[d.w], 1);
}

// -------- scan phase 1 --------
__global__ void part_k() {
    __shared__ int red[256];
    int b = blockIdx.x, t = threadIdx.x;
    int base = b * SCAN_CHUNK;
    int v = 0;
    for (int i = t; i < SCAN_CHUNK; i += 256) {
        int idx = base + i;
        if (idx < NN) v += g_cnt[idx];
    }
    red[t] = v;
    __syncthreads();
    for (int s = 128; s; s >>= 1) { if (t < s) red[t] += red[t + s]; __syncthreads(); }
    if (t == 0) g_part[b] = red[0];
}

// -------- scan phase 2 --------
__global__ void scanpart_k() {
    __shared__ int sp[128];
    int t = threadIdx.x;
    int v = (t < NBLK) ? g_part[t] : 0;
    sp[t] = v;
    __syncthreads();
    for (int off = 1; off < 128; off <<= 1) {
        int u = (t >= off) ? sp[t - off] : 0;
        __syncthreads();
        sp[t] += u;
        __syncthreads();
    }
    if (t < NBLK) g_part[t] = sp[t] - v;
    if (t == 127) g_rowptr[NN] = sp[127];
}

// -------- scan phase 3 --------
__global__ void scan3_k() {
    __shared__ int sp[SCAN_CHUNK];
    int b = blockIdx.x, t = threadIdx.x;
    int idx = b * SCAN_CHUNK + t;
    int v = (idx < NN) ? g_cnt[idx] : 0;
    sp[t] = v;
    __syncthreads();
    for (int off = 1; off < SCAN_CHUNK; off <<= 1) {
        int u = (t >= off) ? sp[t - off] : 0;
        __syncthreads();
        sp[t] += u;
        __syncthreads();
    }
    if (idx < NN) {
        g_rowptr[idx] = g_part[b] + sp[t] - v;
        g_dinv[idx] = rsqrtf((float)v + 1.0f);
    }
}

// -------- CSR fill: 4 edges per thread --------
__global__ void fill_k(const int* __restrict__ w) {
    int t4 = (blockIdx.x * blockDim.x + threadIdx.x) * 4;
    if (t4 >= EE) return;
    int sh = g_shift;
    int4 s = load4idx(w, t4, sh);
    int4 d = load4idx(w, EE + t4, sh);
    g_col[g_rowptr[d.x] + atomicAdd(&g_fill[d.x], 1)] = s.x;
    g_col[g_rowptr[d.y] + atomicAdd(&g_fill[d.y], 1)] = s.y;
    g_col[g_rowptr[d.z] + atomicAdd(&g_fill[d.z], 1)] = s.z;
    g_col[g_rowptr[d.w] + atomicAdd(&g_fill[d.w], 1)] = s.w;
}

// -------- aggregate raw x (F=4): warp per node --------
__global__ void aggx_k(const float* __restrict__ x) {
    int warp = (blockIdx.x * blockDim.x + threadIdx.x) >> 5;
    if (warp >= NN) return;
    int lane = threadIdx.x & 31;
    int s = g_rowptr[warp], e = g_rowptr[warp + 1];
    float4 acc = make_float4(0.f, 0.f, 0.f, 0.f);
    const float4* xv = (const float4*)x;
    for (int p = s + lane; p < e; p += 32) {
        int src = g_col[p];
        float w = g_dinv[src];
        float4 v = xv[src];
        acc.x += w * v.x; acc.y += w * v.y; acc.z += w * v.z; acc.w += w * v.w;
    }
    #pragma unroll
    for (int off = 16; off; off >>= 1) {
        acc.x += __shfl_down_sync(0xffffffffu, acc.x, off);
        acc.y += __shfl_down_sync(0xffffffffu, acc.y, off);
        acc.z += __shfl_down_sync(0xffffffffu, acc.z, off);
        acc.w += __shfl_down_sync(0xffffffffu, acc.w, off);
    }
    if (lane == 0) {
        float di = g_dinv[warp];
        float4 sv = xv[warp];
        float wi = di * di;
        float4 o;
        o.x = acc.x * di + sv.x * wi;
        o.y = acc.y * di + sv.y * wi;
        o.z = acc.z * di + sv.z * wi;
        o.w = acc.w * di + sv.w * wi;
        ((float4*)g_xa)[warp] = o;
    }
}

// -------- layer-1 GEMM: xa[N,4]@W1 + b1, relu, prescale -> g_hA fp16 --------
__global__ void gemm1_k(const float* __restrict__ W1, const float* __restrict__ b1) {
    int idx = blockIdx.x * blockDim.x + threadIdx.x;   // NN*64
    if (idx >= NN * 64) return;
    int node = idx >> 6, jc = idx & 63;
    int j = jc * 2;
    float4 a = ((const float4*)g_xa)[node];
    float acc0 = b1[j]     + a.x * W1[j]     + a.y * W1[128 + j]     + a.z * W1[256 + j]     + a.w * W1[384 + j];
    float acc1 = b1[j + 1] + a.x * W1[j + 1] + a.y * W1[128 + j + 1] + a.z * W1[256 + j + 1] + a.w * W1[384 + j + 1];
    float d = g_dinv[node];
    __half2 h = __floats2half2_rn(fmaxf(acc0, 0.f) * d, fmaxf(acc1, 0.f) * d);
    ((__half2*)g_hA)[node * 64 + jc] = h;
}

// -------- fused GCN layer: pipelined gather -> smem, HMMA GEMM -> fp16 out ----
__global__ __launch_bounds__(256) void layer_k(
    int insel, int wsel, const float* __restrict__ b, int outsel, int prescale) {
    extern __shared__ char dsm[];
    __half* Is  = (__half*)dsm;                  // 64*136*2
    __half* Wsm = (__half*)(dsm + 64 * LDI * 2); // 128*136*2
    int t = threadIdx.x, lane = t & 31, wrp = t >> 5;
    int nodeBase = blockIdx.x * 64;
    const uint2* h2 = (const uint2*)hsel(insel);

    // ---- stage Wt tile into smem ----
    const uint4* Wg = (const uint4*)(g_Wt + wsel * HH * HH);
    for (int i = t; i < HH * 16; i += 256) {
        int row = i >> 4, c8 = i & 15;
        *(uint4*)(Wsm + row * LDW + c8 * 8) = Wg[i];
    }

    // ---- gather phase: warp per node, 4-deep pipelined edge loop ----
    #pragma unroll 1
    for (int r = 0; r < 8; r++) {
        int row = wrp * 8 + r;
        int n = nodeBase + row;
        if (n < NN) {
            int s = g_rowptr[n], e = g_rowptr[n + 1];
            float4 acc = h2x2_to_f4(h2[n * 32 + lane]);   // self-loop term
            int p = s;
            #pragma unroll 1
            for (; p + 4 <= e; p += 4) {
                int s0 = __ldg(&g_col[p]);
                int s1 = __ldg(&g_col[p + 1]);
                int s2 = __ldg(&g_col[p + 2]);
                int s3 = __ldg(&g_col[p + 3]);
                uint2 v0 = h2[s0 * 32 + lane];
                uint2 v1 = h2[s1 * 32 + lane];
                uint2 v2 = h2[s2 * 32 + lane];
                uint2 v3 = h2[s3 * 32 + lane];
                float4 f0 = h2x2_to_f4(v0), f1 = h2x2_to_f4(v1);
                float4 f2 = h2x2_to_f4(v2), f3 = h2x2_to_f4(v3);
                f0.x += f1.x; f0.y += f1.y; f0.z += f1.z; f0.w += f1.w;
                f2.x += f3.x; f2.y += f3.y; f2.z += f3.z; f2.w += f3.w;
                acc.x += f0.x + f2.x; acc.y += f0.y + f2.y;
                acc.z += f0.z + f2.z; acc.w += f0.w + f2.w;
            }
            #pragma unroll 1
            for (; p < e; p++) {
                int src = __ldg(&g_col[p]);
                float4 f = h2x2_to_f4(h2[src * 32 + lane]);
                acc.x += f.x; acc.y += f.y; acc.z += f.z; acc.w += f.w;
            }
            float d = g_dinv[n];
            __half2 p0 = __floats2half2_rn(acc.x * d, acc.y * d);
            __half2 p1 = __floats2half2_rn(acc.z * d, acc.w * d);
            uint2 st;
            st.x = *(unsigned*)&p0;
            st.y = *(unsigned*)&p1;
            ((uint2*)(Is + row * LDI))[lane] = st;
        } else {
            ((uint2*)(Is + row * LDI))[lane] = make_uint2(0u, 0u);
        }
    }
    __syncthreads();

    // ---- GEMM: Is[64,128] @ Wt^T via mma.m16n8k16 ----
    int mtile = wrp & 3;
    int nhalf = wrp >> 2;
    unsigned a_base = (unsigned)__cvta_generic_to_shared(
        Is + (mtile * 16 + (lane & 15)) * LDI + (lane >> 4) * 8);
    unsigned b_base = (unsigned)__cvta_generic_to_shared(
        Wsm + (nhalf * 64 + (lane & 7)) * LDW + ((lane >> 3) & 1) * 8);

    float acc[8][4];
    #pragma unroll
    for (int i = 0; i < 8; i++)
        #pragma unroll
        for (int j = 0; j < 4; j++) acc[i][j] = 0.f;

    #pragma unroll
    for (int k = 0; k < 8; k++) {
        unsigned a0, a1, a2, a3;
        ldsm_x4(a0, a1, a2, a3, a_base + k * 32);
        #pragma unroll
        for (int n8 = 0; n8 < 8; n8++) {
            unsigned b0, b1;
            ldsm_x2(b0, b1, b_base + n8 * 8 * LDW * 2 + k * 32);
            mma16816(acc[n8], a0, a1, a2, a3, b0, b1);
        }
    }

    // ---- epilogue ----
    int mr = lane >> 2;
    int nc = (lane & 3) * 2;
    int node0 = nodeBase + mtile * 16 + mr;
    int node1 = node0 + 8;
    bool v0 = node0 < NN, v1 = node1 < NN;
    float d0 = 1.f, d1 = 1.f;
    if (prescale) {
        if (v0) d0 = g_dinv[node0];
        if (v1) d1 = g_dinv[node1];
    }
    __half* hout = hsel(outsel);
    #pragma unroll
    for (int n8 = 0; n8 < 8; n8++) {
        int n = nhalf * 64 + n8 * 8 + nc;
        float2 bb = *(const float2*)&b[n];
        if (v0) {
            __half2 p = __floats2half2_rn(fmaxf(acc[n8][0] + bb.x, 0.f) * d0,
                                          fmaxf(acc[n8][1] + bb.y, 0.f) * d0);
            *(__half2*)(hout + node0 * HH + n) = p;
        }
        if (v1) {
            __half2 p = __floats2half2_rn(fmaxf(acc[n8][2] + bb.x, 0.f) * d1,
                                          fmaxf(acc[n8][3] + bb.y, 0.f) * d1);
            *(__half2*)(hout + node1 * HH + n) = p;
        }
    }
}

// -------- global mean pool: segment-accumulate (batch sorted) --------
__global__ void pool_k(const int* __restrict__ wbatch, int insel) {
    int warp = (blockIdx.x * blockDim.x + threadIdx.x) >> 5;
    int lane = threadIdx.x & 31;
    int base = warp * 16;
    if (base >= NN) return;
    int sh = g_shift;
    const uint2* hv = (const uint2*)hsel(insel);
    int end = base + 16; if (end > NN) end = NN;
    float4 acc = make_float4(0.f, 0.f, 0.f, 0.f);
    int cur = wbatch[base << sh];
    int cnt = 0;
    for (int n = base; n < end; n++) {
        int g = wbatch[n << sh];
        if (g != cur) {
            float* bp = &g_pooled[cur * HH + lane * 4];
            atomicAdd(bp + 0, acc.x); atomicAdd(bp + 1, acc.y);
            atomicAdd(bp + 2, acc.z); atomicAdd(bp + 3, acc.w);
            if (lane == 0) atomicAdd(&g_gcnt[cur], (float)cnt);
            acc = make_float4(0.f, 0.f, 0.f, 0.f);
            cnt = 0; cur = g;
        }
        float4 f = h2x2_to_f4(hv[n * 32 + lane]);
        acc.x += f.x; acc.y += f.y; acc.z += f.z; acc.w += f.w;
        cnt++;
    }
    float* bp = &g_pooled[cur * HH + lane * 4];
    atomicAdd(bp + 0, acc.x); atomicAdd(bp + 1, acc.y);
    atomicAdd(bp + 2, acc.z); atomicAdd(bp + 3, acc.w);
    if (lane == 0) atomicAdd(&g_gcnt[cur], (float)cnt);
}

// -------- classifier head --------
__global__ void final_k(const float* __restrict__ Wl, const float* __restrict__ bl,
                        float* __restrict__ out) {
    int idx = blockIdx.x * blockDim.x + threadIdx.x;
    if (idx >= GG * CC) return;
    int g = idx / CC, c = idx % CC;
    float inv = 1.0f / fmaxf(g_gcnt[g], 1.0f);
    float acc = bl[c];
    const float* pr = &g_pooled[g * HH];
    #pragma unroll 4
    for (int k = 0; k < HH; k++) acc += pr[k] * inv * Wl[k * CC + c];
    out[idx] = 1.0f / (1.0f + expf(-acc));
}

extern "C" void kernel_launch(void* const* d_in, const int* in_sizes, int n_in,
                              void* d_out, int out_size) {
    const float* x    = (const float*)d_in[0];
    const int*   eiw  = (const int*)d_in[1];
    const int*   batw = (const int*)d_in[2];
    const float* W1 = (const float*)d_in[3];
    const float* b1 = (const float*)d_in[4];
    const float* W2 = (const float*)d_in[5];
    const float* b2 = (const float*)d_in[6];
    const float* W3 = (const float*)d_in[7];
    const float* b3 = (const float*)d_in[8];
    const float* W4 = (const float*)d_in[9];
    const float* b4 = (const float*)d_in[10];
    const float* Wl = (const float*)d_in[11];
    const float* bl = (const float*)d_in[12];
    float* out = (float*)d_out;

    const int LAYER_SMEM = (64 * LDI + HH * LDW) * 2;   // 52224 B
    static int attr_done = 0;
    if (!attr_done) {
        cudaFuncSetAttribute(layer_k, cudaFuncAttributeMaxDynamicSharedMemorySize, LAYER_SMEM);
        attr_done = 1;
    }

    // ---- dtype detect + weight convert + CSR build ----
    detect_k<<<1, 256>>>(eiw);
    zero_k<<<(NN + 255) / 256, 256>>>();
    wcvt_k<<<(3 * HH * HH + 255) / 256, 256>>>(W2, W3, W4);
    count_k<<<(EE / 4 + 255) / 256, 256>>>(eiw);
    part_k<<<NBLK, 256>>>();
    scanpart_k<<<1, 128>>>();
    scan3_k<<<NBLK, SCAN_CHUNK>>>();
    fill_k<<<(EE / 4 + 255) / 256, 256>>>(eiw);

    const int WARP_BLOCKS = (NN * 32 + 255) / 256;
    const int LAYER_BLOCKS = (NN + 63) / 64;

    // ---- layer 1 ----
    aggx_k<<<WARP_BLOCKS, 256>>>(x);
    gemm1_k<<<(NN * 64 + 255) / 256, 256>>>(W1, b1);

    // ---- layers 2-4 (ping-pong A<->B) ----
    layer_k<<<LAYER_BLOCKS, 256, LAYER_SMEM>>>(0, 0, b2, 1, 1);
    layer_k<<<LAYER_BLOCKS, 256, LAYER_SMEM>>>(1, 1, b3, 0, 1);
    layer_k<<<LAYER_BLOCKS, 256, LAYER_SMEM>>>(0, 2, b4, 1, 0);

    // ---- pool + head ----
    const int POOL_BLOCKS = ((NN + 15) / 16 * 32 + 255) / 256;
    pool_k<<<POOL_BLOCKS, 256>>>(batw, 1);
    final_k<<<(GG * CC + 255) / 256, 256>>>(Wl, bl, out);
}

// round 6
// speedup vs baseline: 1.0809x; 1.0809x over previous
#include <cuda_runtime.h>
#include <cuda_fp16.h>
#include <cuda_fp8.h>
#include <math.h>

#define NN 100000
#define EE 1600000
#define HH 128
#define GG 256
#define CC 5
#define SCAN_CHUNK 1024
#define NBLK ((NN + SCAN_CHUNK - 1) / SCAN_CHUNK)   // 98
#define LDI 136   // smem A-tile stride in halves
#define LDW 136   // smem W-tile stride in halves

// -------- device scratch (static, allocation-free) --------
__device__ __align__(16) unsigned char g_q0[NN * HH];   // fp8 e4m3 messages
__device__ __align__(16) unsigned char g_q1[NN * HH];   // fp8 e4m3 messages
__device__ __align__(16) __half g_hF[NN * HH];          // final layer output fp16
__device__ __align__(16) __half g_Wt[3 * HH * HH];      // fp16 weights, transposed [n][k]
__device__ __align__(16) float  g_xa[NN * 4];
__device__ int   g_cnt[NN];
__device__ int   g_fill[NN];
__device__ int   g_rowptr[NN + 1];
__device__ int   g_col[EE];
__device__ float g_dinv[NN];
__device__ int   g_part[NBLK];
__device__ __align__(16) float g_pooled[GG * HH];
__device__ float g_gcnt[GG];
__device__ int   g_shift;   // 0: int32 indices, 1: int64 (read low word)

__device__ __forceinline__ const unsigned* qsel(int k) {
    return (const unsigned*)(k ? g_q1 : g_q0);
}

// -------- fp8 helpers --------
__device__ __forceinline__ float4 q4_to_f4(unsigned v) {
    __half2_raw lo = __nv_cvt_fp8x2_to_halfraw2((__nv_fp8x2_storage_t)(v & 0xffffu), __NV_E4M3);
    __half2_raw hi = __nv_cvt_fp8x2_to_halfraw2((__nv_fp8x2_storage_t)(v >> 16), __NV_E4M3);
    float2 a = __half22float2(*(__half2*)&lo);
    float2 b = __half22float2(*(__half2*)&hi);
    return make_float4(a.x, a.y, b.x, b.y);
}
__device__ __forceinline__ unsigned f4_to_q4(float4 f) {
    unsigned short lo = __nv_cvt_float2_to_fp8x2(make_float2(f.x, f.y), __NV_SATFINITE, __NV_E4M3);
    unsigned short hi = __nv_cvt_float2_to_fp8x2(make_float2(f.z, f.w), __NV_SATFINITE, __NV_E4M3);
    return (unsigned)lo | ((unsigned)hi << 16);
}

// -------- tensor-core helpers --------
__device__ __forceinline__ void ldsm_x4(unsigned &r0, unsigned &r1, unsigned &r2, unsigned &r3,
                                        unsigned addr) {
    asm volatile("ldmatrix.sync.aligned.m8n8.x4.shared.b16 {%0,%1,%2,%3},[%4];"
                 : "=r"(r0), "=r"(r1), "=r"(r2), "=r"(r3) : "r"(addr));
}
__device__ __forceinline__ void ldsm_x2(unsigned &r0, unsigned &r1, unsigned addr) {
    asm volatile("ldmatrix.sync.aligned.m8n8.x2.shared.b16 {%0,%1},[%2];"
                 : "=r"(r0), "=r"(r1) : "r"(addr));
}
__device__ __forceinline__ void mma16816(float* c, unsigned a0, unsigned a1, unsigned a2,
                                         unsigned a3, unsigned b0, unsigned b1) {
    asm volatile("mma.sync.aligned.m16n8k16.row.col.f32.f16.f16.f32 "
                 "{%0,%1,%2,%3},{%4,%5,%6,%7},{%8,%9},{%0,%1,%2,%3};"
                 : "+f"(c[0]), "+f"(c[1]), "+f"(c[2]), "+f"(c[3])
                 : "r"(a0), "r"(a1), "r"(a2), "r"(a3), "r"(b0), "r"(b1));
}

// -------- dtype detection --------
__global__ void detect_k(const int* __restrict__ w) {
    __shared__ int sor[256];
    int t = threadIdx.x;
    int o = 0;
    #pragma unroll
    for (int k = 0; k < 16; k++) {
        int j = (t * 16 + k) * (EE / 4096);
        o |= w[2 * j + 1];
    }
    sor[t] = o;
    __syncthreads();
    for (int s = 128; s; s >>= 1) { if (t < s) sor[t] |= sor[t + s]; __syncthreads(); }
    if (t == 0) g_shift = (sor[0] == 0) ? 1 : 0;
}

// -------- zero scratch --------
__global__ void zero_k() {
    int i = blockIdx.x * blockDim.x + threadIdx.x;
    if (i < NN) { g_cnt[i] = 0; g_fill[i] = 0; }
    if (i < GG * HH) g_pooled[i] = 0.0f;
    if (i < GG) g_gcnt[i] = 0.0f;
}

// -------- weight convert: W[k][n] fp32 -> Wt[n][k] fp16 --------
__global__ void wcvt_k(const float* __restrict__ W2, const float* __restrict__ W3,
                       const float* __restrict__ W4) {
    int idx = blockIdx.x * blockDim.x + threadIdx.x;
    if (idx >= 3 * HH * HH) return;
    int sel = idx >> 14;
    int loc = idx & 16383;
    int n = loc >> 7, k = loc & 127;
    const float* s = (sel == 0) ? W2 : (sel == 1) ? W3 : W4;
    g_Wt[idx] = __float2half(s[k * HH + n]);
}

// -------- degree count --------
__global__ void count_k(const int* __restrict__ w) {
    int e = blockIdx.x * blockDim.x + threadIdx.x;
    if (e >= EE) return;
    int sh = g_shift;
    int dst = w[(EE + e) << sh];
    atomicAdd(&g_cnt[dst], 1);
}

// -------- scan phase 1 --------
__global__ void part_k() {
    __shared__ int red[256];
    int b = blockIdx.x, t = threadIdx.x;
    int base = b * SCAN_CHUNK;
    int v = 0;
    for (int i = t; i < SCAN_CHUNK; i += 256) {
        int idx = base + i;
        if (idx < NN) v += g_cnt[idx];
    }
    red[t] = v;
    __syncthreads();
    for (int s = 128; s; s >>= 1) { if (t < s) red[t] += red[t + s]; __syncthreads(); }
    if (t == 0) g_part[b] = red[0];
}

// -------- scan phase 2 --------
__global__ void scanpart_k() {
    __shared__ int sp[128];
    int t = threadIdx.x;
    int v = (t < NBLK) ? g_part[t] : 0;
    sp[t] = v;
    __syncthreads();
    for (int off = 1; off < 128; off <<= 1) {
        int u = (t >= off) ? sp[t - off] : 0;
        __syncthreads();
        sp[t] += u;
        __syncthreads();
    }
    if (t < NBLK) g_part[t] = sp[t] - v;
    if (t == 127) g_rowptr[NN] = sp[127];
}

// -------- scan phase 3 --------
__global__ void scan3_k() {
    __shared__ int sp[SCAN_CHUNK];
    int b = blockIdx.x, t = threadIdx.x;
    int idx = b * SCAN_CHUNK + t;
    int v = (idx < NN) ? g_cnt[idx] : 0;
    sp[t] = v;
    __syncthreads();
    for (int off = 1; off < SCAN_CHUNK; off <<= 1) {
        int u = (t >= off) ? sp[t - off] : 0;
        __syncthreads();
        sp[t] += u;
        __syncthreads();
    }
    if (idx < NN) {
        g_rowptr[idx] = g_part[b] + sp[t] - v;
        g_dinv[idx] = rsqrtf((float)v + 1.0f);
    }
}

// -------- CSR fill --------
__global__ void fill_k(const int* __restrict__ w) {
    int e = blockIdx.x * blockDim.x + threadIdx.x;
    if (e >= EE) return;
    int sh = g_shift;
    int src = w[e << sh];
    int dst = w[(EE + e) << sh];
    int pos = g_rowptr[dst] + atomicAdd(&g_fill[dst], 1);
    g_col[pos] = src;
}

// -------- aggregate raw x (F=4): warp per node --------
__global__ void aggx_k(const float* __restrict__ x) {
    int warp = (blockIdx.x * blockDim.x + threadIdx.x) >> 5;
    if (warp >= NN) return;
    int lane = threadIdx.x & 31;
    int s = g_rowptr[warp], e = g_rowptr[warp + 1];
    float4 acc = make_float4(0.f, 0.f, 0.f, 0.f);
    const float4* xv = (const float4*)x;
    for (int p = s + lane; p < e; p += 32) {
        int src = g_col[p];
        float w = g_dinv[src];
        float4 v = xv[src];
        acc.x += w * v.x; acc.y += w * v.y; acc.z += w * v.z; acc.w += w * v.w;
    }
    #pragma unroll
    for (int off = 16; off; off >>= 1) {
        acc.x += __shfl_down_sync(0xffffffffu, acc.x, off);
        acc.y += __shfl_down_sync(0xffffffffu, acc.y, off);
        acc.z += __shfl_down_sync(0xffffffffu, acc.z, off);
        acc.w += __shfl_down_sync(0xffffffffu, acc.w, off);
    }
    if (lane == 0) {
        float di = g_dinv[warp];
        float4 sv = xv[warp];
        float wi = di * di;
        float4 o;
        o.x = acc.x * di + sv.x * wi;
        o.y = acc.y * di + sv.y * wi;
        o.z = acc.z * di + sv.z * wi;
        o.w = acc.w * di + sv.w * wi;
        ((float4*)g_xa)[warp] = o;
    }
}

// -------- layer-1 GEMM: xa[N,4]@W1 + b1, relu, prescale -> g_q0 fp8 --------
__global__ void gemm1_k(const float* __restrict__ W1, const float* __restrict__ b1) {
    int idx = blockIdx.x * blockDim.x + threadIdx.x;   // NN*32
    if (idx >= NN * 32) return;
    int node = idx >> 5, jc = idx & 31;
    int j = jc * 4;
    float4 a = ((const float4*)g_xa)[node];
    float d = g_dinv[node];
    float4 o;
    float* op = &o.x;
    #pragma unroll
    for (int u = 0; u < 4; u++) {
        float acc = b1[j + u] + a.x * W1[j + u] + a.y * W1[128 + j + u]
                  + a.z * W1[256 + j + u] + a.w * W1[384 + j + u];
        op[u] = fmaxf(acc, 0.f) * d;
    }
    ((unsigned*)g_q0)[node * 32 + jc] = f4_to_q4(o);
}

// -------- fused GCN layer: fp8 gather -> smem fp16 A-tile, HMMA -> fp8/fp16 out ----
// 64 nodes/block, 256 threads. outmode: 0 -> g_q0 (fp8), 1 -> g_q1 (fp8), 2 -> g_hF (fp16).
__global__ __launch_bounds__(256) void layer_k(
    int insel, int wsel, const float* __restrict__ b, int outmode, int prescale) {
    extern __shared__ char dsm[];
    __half* Is  = (__half*)dsm;                  // 64*136*2
    __half* Wsm = (__half*)(dsm + 64 * LDI * 2); // 128*136*2
    int t = threadIdx.x, lane = t & 31, wrp = t >> 5;
    int nodeBase = blockIdx.x * 64;
    const unsigned* q = qsel(insel);

    // ---- stage Wt tile into smem ----
    const uint4* Wg = (const uint4*)(g_Wt + wsel * HH * HH);
    for (int i = t; i < HH * 16; i += 256) {
        int row = i >> 4, c8 = i & 15;
        *(uint4*)(Wsm + row * LDW + c8 * 8) = Wg[i];
    }

    // ---- gather phase: warp per node, lane covers 4 features (4B fp8) ----
    #pragma unroll 1
    for (int r = 0; r < 8; r++) {
        int row = wrp * 8 + r;
        int n = nodeBase + row;
        if (n < NN) {
            int s = g_rowptr[n], e = g_rowptr[n + 1];
            float4 acc = q4_to_f4(q[n * 32 + lane]);   // self-loop term
            for (int p = s; p < e; p++) {
                int src = __ldg(&g_col[p]);
                float4 f = q4_to_f4(q[src * 32 + lane]);
                acc.x += f.x; acc.y += f.y; acc.z += f.z; acc.w += f.w;
            }
            float d = g_dinv[n];
            __half2 p0 = __floats2half2_rn(acc.x * d, acc.y * d);
            __half2 p1 = __floats2half2_rn(acc.z * d, acc.w * d);
            uint2 st;
            st.x = *(unsigned*)&p0;
            st.y = *(unsigned*)&p1;
            ((uint2*)(Is + row * LDI))[lane] = st;
        } else {
            ((uint2*)(Is + row * LDI))[lane] = make_uint2(0u, 0u);
        }
    }
    __syncthreads();

    // ---- GEMM: Is[64,128] @ Wt^T via mma.m16n8k16 ----
    int mtile = wrp & 3;
    int nhalf = wrp >> 2;
    unsigned a_base = (unsigned)__cvta_generic_to_shared(
        Is + (mtile * 16 + (lane & 15)) * LDI + (lane >> 4) * 8);
    unsigned b_base = (unsigned)__cvta_generic_to_shared(
        Wsm + (nhalf * 64 + (lane & 7)) * LDW + ((lane >> 3) & 1) * 8);

    float acc[8][4];
    #pragma unroll
    for (int i = 0; i < 8; i++)
        #pragma unroll
        for (int j = 0; j < 4; j++) acc[i][j] = 0.f;

    #pragma unroll
    for (int k = 0; k < 8; k++) {
        unsigned a0, a1, a2, a3;
        ldsm_x4(a0, a1, a2, a3, a_base + k * 32);
        #pragma unroll
        for (int n8 = 0; n8 < 8; n8++) {
            unsigned b0, b1;
            ldsm_x2(b0, b1, b_base + n8 * 8 * LDW * 2 + k * 32);
            mma16816(acc[n8], a0, a1, a2, a3, b0, b1);
        }
    }

    // ---- epilogue: bias, relu, (prescale, fp8) or fp16 store ----
    int mr = lane >> 2;
    int nc = (lane & 3) * 2;
    int node0 = nodeBase + mtile * 16 + mr;
    int node1 = node0 + 8;
    bool v0 = node0 < NN, v1 = node1 < NN;
    float d0 = 1.f, d1 = 1.f;
    if (prescale) {
        if (v0) d0 = g_dinv[node0];
        if (v1) d1 = g_dinv[node1];
    }
    unsigned short* qout = (unsigned short*)(outmode ? g_q1 : g_q0);
    #pragma unroll
    for (int n8 = 0; n8 < 8; n8++) {
        int n = nhalf * 64 + n8 * 8 + nc;
        float2 bb = *(const float2*)&b[n];
        float o00 = fmaxf(acc[n8][0] + bb.x, 0.f) * d0;
        float o01 = fmaxf(acc[n8][1] + bb.y, 0.f) * d0;
        float o10 = fmaxf(acc[n8][2] + bb.x, 0.f) * d1;
        float o11 = fmaxf(acc[n8][3] + bb.y, 0.f) * d1;
        if (outmode == 2) {
            if (v0) *(__half2*)(g_hF + node0 * HH + n) = __floats2half2_rn(o00, o01);
            if (v1) *(__half2*)(g_hF + node1 * HH + n) = __floats2half2_rn(o10, o11);
        } else {
            if (v0) qout[(node0 * HH + n) >> 1] =
                __nv_cvt_float2_to_fp8x2(make_float2(o00, o01), __NV_SATFINITE, __NV_E4M3);
            if (v1) qout[(node1 * HH + n) >> 1] =
                __nv_cvt_float2_to_fp8x2(make_float2(o10, o11), __NV_SATFINITE, __NV_E4M3);
        }
    }
}

// -------- global mean pool: segment-accumulate (batch sorted), reads g_hF --------
__global__ void pool_k(const int* __restrict__ wbatch) {
    int warp = (blockIdx.x * blockDim.x + threadIdx.x) >> 5;
    int lane = threadIdx.x & 31;
    int base = warp * 16;
    if (base >= NN) return;
    int sh = g_shift;
    const uint2* hv = (const uint2*)g_hF;
    int end = base + 16; if (end > NN) end = NN;
    float4 acc = make_float4(0.f, 0.f, 0.f, 0.f);
    int cur = wbatch[base << sh];
    int cnt = 0;
    for (int n = base; n < end; n++) {
        int g = wbatch[n << sh];
        if (g != cur) {
            float* bp = &g_pooled[cur * HH + lane * 4];
            atomicAdd(bp + 0, acc.x); atomicAdd(bp + 1, acc.y);
            atomicAdd(bp + 2, acc.z); atomicAdd(bp + 3, acc.w);
            if (lane == 0) atomicAdd(&g_gcnt[cur], (float)cnt);
            acc = make_float4(0.f, 0.f, 0.f, 0.f);
            cnt = 0; cur = g;
        }
        uint2 v = hv[n * 32 + lane];
        float2 lo = __half22float2(*(const __half2*)&v.x);
        float2 hi = __half22float2(*(const __half2*)&v.y);
        acc.x += lo.x; acc.y += lo.y; acc.z += hi.x; acc.w += hi.y;
        cnt++;
    }
    float* bp = &g_pooled[cur * HH + lane * 4];
    atomicAdd(bp + 0, acc.x); atomicAdd(bp + 1, acc.y);
    atomicAdd(bp + 2, acc.z); atomicAdd(bp + 3, acc.w);
    if (lane == 0) atomicAdd(&g_gcnt[cur], (float)cnt);
}

// -------- classifier head --------
__global__ void final_k(const float* __restrict__ Wl, const float* __restrict__ bl,
                        float* __restrict__ out) {
    int idx = blockIdx.x * blockDim.x + threadIdx.x;
    if (idx >= GG * CC) return;
    int g = idx / CC, c = idx % CC;
    float inv = 1.0f / fmaxf(g_gcnt[g], 1.0f);
    float acc = bl[c];
    const float* pr = &g_pooled[g * HH];
    #pragma unroll 4
    for (int k = 0; k < HH; k++) acc += pr[k] * inv * Wl[k * CC + c];
    out[idx] = 1.0f / (1.0f + expf(-acc));
}

extern "C" void kernel_launch(void* const* d_in, const int* in_sizes, int n_in,
                              void* d_out, int out_size) {
    const float* x    = (const float*)d_in[0];
    const int*   eiw  = (const int*)d_in[1];
    const int*   batw = (const int*)d_in[2];
    const float* W1 = (const float*)d_in[3];
    const float* b1 = (const float*)d_in[4];
    const float* W2 = (const float*)d_in[5];
    const float* b2 = (const float*)d_in[6];
    const float* W3 = (const float*)d_in[7];
    const float* b3 = (const float*)d_in[8];
    const float* W4 = (const float*)d_in[9];
    const float* b4 = (const float*)d_in[10];
    const float* Wl = (const float*)d_in[11];
    const float* bl = (const float*)d_in[12];
    float* out = (float*)d_out;

    const int LAYER_SMEM = (64 * LDI + HH * LDW) * 2;   // 52224 B
    static int attr_done = 0;
    if (!attr_done) {
        cudaFuncSetAttribute(layer_k, cudaFuncAttributeMaxDynamicSharedMemorySize, LAYER_SMEM);
        attr_done = 1;
    }

    // ---- dtype detect + weight convert + CSR build ----
    detect_k<<<1, 256>>>(eiw);
    zero_k<<<(NN + 255) / 256, 256>>>();
    wcvt_k<<<(3 * HH * HH + 255) / 256, 256>>>(W2, W3, W4);
    count_k<<<(EE + 255) / 256, 256>>>(eiw);
    part_k<<<NBLK, 256>>>();
    scanpart_k<<<1, 128>>>();
    scan3_k<<<NBLK, SCAN_CHUNK>>>();
    fill_k<<<(EE + 255) / 256, 256>>>(eiw);

    const int WARP_BLOCKS = (NN * 32 + 255) / 256;
    const int LAYER_BLOCKS = (NN + 63) / 64;

    // ---- layer 1: aggregate x (F=4), GEMM W1 -> g_q0 (prescaled fp8) ----
    aggx_k<<<WARP_BLOCKS, 256>>>(x);
    gemm1_k<<<(NN * 32 + 255) / 256, 256>>>(W1, b1);

    // ---- layers 2-4: fused fp8 gather + HMMA (q0 -> q1 -> q0 -> hF) ----
    layer_k<<<LAYER_BLOCKS, 256, LAYER_SMEM>>>(0, 0, b2, 1, 1);
    layer_k<<<LAYER_BLOCKS, 256, LAYER_SMEM>>>(1, 1, b3, 0, 1);
    layer_k<<<LAYER_BLOCKS, 256, LAYER_SMEM>>>(0, 2, b4, 2, 0);   // last: fp16 out, no prescale

    // ---- pool + head ----
    const int POOL_BLOCKS = ((NN + 15) / 16 * 32 + 255) / 256;
    pool_k<<<POOL_BLOCKS, 256>>>(batw);
    final_k<<<(GG * CC + 255) / 256, 256>>>(Wl, bl, out);
}

// round 7
// speedup vs baseline: 1.1721x; 1.0844x over previous
#include <cuda_runtime.h>
#include <cuda_fp16.h>
#include <cuda_fp8.h>
#include <math.h>

#define NN 100000
#define EE 1600000
#define HH 128
#define GG 256
#define CC 5
#define SCAN_CHUNK 1024
#define NBLK ((NN + SCAN_CHUNK - 1) / SCAN_CHUNK)   // 98
#define LDI 136   // smem A-tile stride in halves

// -------- device scratch (static, allocation-free) --------
__device__ __align__(16) unsigned char g_q0[NN * HH];   // fp8 e4m3 messages
__device__ __align__(16) unsigned char g_q1[NN * HH];   // fp8 e4m3 messages
__device__ __align__(16) __half g_hF[NN * HH];          // final layer output fp16
__device__ __align__(16) uint2 g_Wf[3 * 4096];          // W in mma B-fragment order
__device__ __align__(16) float  g_xa[NN * 4];
__device__ int   g_cnt[NN];
__device__ int   g_fill[NN];
__device__ int   g_rowptr[NN + 1];
__device__ int   g_col[EE];
__device__ float g_dinv[NN];
__device__ int   g_part[NBLK];
__device__ __align__(16) float g_pooled[GG * HH];
__device__ float g_gcnt[GG];
__device__ int   g_shift;   // 0: int32 indices, 1: int64 (read low word)

__device__ __forceinline__ const unsigned* qsel(int k) {
    return (const unsigned*)(k ? g_q1 : g_q0);
}

// -------- fp8 helpers --------
__device__ __forceinline__ float4 q4_to_f4(unsigned v) {
    __half2_raw lo = __nv_cvt_fp8x2_to_halfraw2((__nv_fp8x2_storage_t)(v & 0xffffu), __NV_E4M3);
    __half2_raw hi = __nv_cvt_fp8x2_to_halfraw2((__nv_fp8x2_storage_t)(v >> 16), __NV_E4M3);
    float2 a = __half22float2(*(__half2*)&lo);
    float2 b = __half22float2(*(__half2*)&hi);
    return make_float4(a.x, a.y, b.x, b.y);
}

// -------- tensor-core helpers --------
__device__ __forceinline__ void ldsm_x4(unsigned &r0, unsigned &r1, unsigned &r2, unsigned &r3,
                                        unsigned addr) {
    asm volatile("ldmatrix.sync.aligned.m8n8.x4.shared.b16 {%0,%1,%2,%3},[%4];"
                 : "=r"(r0), "=r"(r1), "=r"(r2), "=r"(r3) : "r"(addr));
}
__device__ __forceinline__ void mma16816(float* c, unsigned a0, unsigned a1, unsigned a2,
                                         unsigned a3, unsigned b0, unsigned b1) {
    asm volatile("mma.sync.aligned.m16n8k16.row.col.f32.f16.f16.f32 "
                 "{%0,%1,%2,%3},{%4,%5,%6,%7},{%8,%9},{%0,%1,%2,%3};"
                 : "+f"(c[0]), "+f"(c[1]), "+f"(c[2]), "+f"(c[3])
                 : "r"(a0), "r"(a1), "r"(a2), "r"(a3), "r"(b0), "r"(b1));
}

// -------- dtype detection --------
__global__ void detect_k(const int* __restrict__ w) {
    __shared__ int sor[256];
    int t = threadIdx.x;
    int o = 0;
    #pragma unroll
    for (int k = 0; k < 16; k++) {
        int j = (t * 16 + k) * (EE / 4096);
        o |= w[2 * j + 1];
    }
    sor[t] = o;
    __syncthreads();
    for (int s = 128; s; s >>= 1) { if (t < s) sor[t] |= sor[t + s]; __syncthreads(); }
    if (t == 0) g_shift = (sor[0] == 0) ? 1 : 0;
}

// -------- zero scratch --------
__global__ void zero_k() {
    int i = blockIdx.x * blockDim.x + threadIdx.x;
    if (i < NN) { g_cnt[i] = 0; g_fill[i] = 0; }
    if (i < GG * HH) g_pooled[i] = 0.0f;
    if (i < GG) g_gcnt[i] = 0.0f;
}

// -------- weight convert: W[k][n] fp32 -> mma B-fragment order fp16 --------
// index = sel*4096 + (kb*16 + n8g)*32 + lane
// u.x = half2(W[kb*16 + 2*(l%4)    ][n], W[kb*16 + 2*(l%4)+1][n])
// u.y = half2(W[kb*16 + 2*(l%4) + 8][n], W[kb*16 + 2*(l%4)+9][n]),  n = n8g*8 + l/4
__global__ void wcvt_k(const float* __restrict__ W2, const float* __restrict__ W3,
                       const float* __restrict__ W4) {
    int idx = blockIdx.x * blockDim.x + threadIdx.x;
    if (idx >= 3 * 4096) return;
    int sel = idx >> 12;
    int r = idx & 4095;
    int kb = r >> 9;
    int n8g = (r >> 5) & 15;
    int l = r & 31;
    int n = n8g * 8 + (l >> 2);
    int k0 = kb * 16 + 2 * (l & 3);
    const float* s = (sel == 0) ? W2 : (sel == 1) ? W3 : W4;
    __half2 p0 = __floats2half2_rn(s[k0 * HH + n], s[(k0 + 1) * HH + n]);
    __half2 p1 = __floats2half2_rn(s[(k0 + 8) * HH + n], s[(k0 + 9) * HH + n]);
    uint2 u;
    u.x = *(unsigned*)&p0;
    u.y = *(unsigned*)&p1;
    g_Wf[idx] = u;
}

// -------- degree count --------
__global__ void count_k(const int* __restrict__ w) {
    int e = blockIdx.x * blockDim.x + threadIdx.x;
    if (e >= EE) return;
    int sh = g_shift;
    int dst = w[(EE + e) << sh];
    atomicAdd(&g_cnt[dst], 1);
}

// -------- scan phase 1 --------
__global__ void part_k() {
    __shared__ int red[256];
    int b = blockIdx.x, t = threadIdx.x;
    int base = b * SCAN_CHUNK;
    int v = 0;
    for (int i = t; i < SCAN_CHUNK; i += 256) {
        int idx = base + i;
        if (idx < NN) v += g_cnt[idx];
    }
    red[t] = v;
    __syncthreads();
    for (int s = 128; s; s >>= 1) { if (t < s) red[t] += red[t + s]; __syncthreads(); }
    if (t == 0) g_part[b] = red[0];
}

// -------- scan phase 2 --------
__global__ void scanpart_k() {
    __shared__ int sp[128];
    int t = threadIdx.x;
    int v = (t < NBLK) ? g_part[t] : 0;
    sp[t] = v;
    __syncthreads();
    for (int off = 1; off < 128; off <<= 1) {
        int u = (t >= off) ? sp[t - off] : 0;
        __syncthreads();
        sp[t] += u;
        __syncthreads();
    }
    if (t < NBLK) g_part[t] = sp[t] - v;
    if (t == 127) g_rowptr[NN] = sp[127];
}

// -------- scan phase 3 --------
__global__ void scan3_k() {
    __shared__ int sp[SCAN_CHUNK];
    int b = blockIdx.x, t = threadIdx.x;
    int idx = b * SCAN_CHUNK + t;
    int v = (idx < NN) ? g_cnt[idx] : 0;
    sp[t] = v;
    __syncthreads();
    for (int off = 1; off < SCAN_CHUNK; off <<= 1) {
        int u = (t >= off) ? sp[t - off] : 0;
        __syncthreads();
        sp[t] += u;
        __syncthreads();
    }
    if (idx < NN) {
        g_rowptr[idx] = g_part[b] + sp[t] - v;
        g_dinv[idx] = rsqrtf((float)v + 1.0f);
    }
}

// -------- CSR fill --------
__global__ void fill_k(const int* __restrict__ w) {
    int e = blockIdx.x * blockDim.x + threadIdx.x;
    if (e >= EE) return;
    int sh = g_shift;
    int src = w[e << sh];
    int dst = w[(EE + e) << sh];
    int pos = g_rowptr[dst] + atomicAdd(&g_fill[dst], 1);
    g_col[pos] = src;
}

// -------- aggregate raw x (F=4): warp per node --------
__global__ void aggx_k(const float* __restrict__ x) {
    int warp = (blockIdx.x * blockDim.x + threadIdx.x) >> 5;
    if (warp >= NN) return;
    int lane = threadIdx.x & 31;
    int s = g_rowptr[warp], e = g_rowptr[warp + 1];
    float4 acc = make_float4(0.f, 0.f, 0.f, 0.f);
    const float4* xv = (const float4*)x;
    for (int p = s + lane; p < e; p += 32) {
        int src = g_col[p];
        float w = g_dinv[src];
        float4 v = xv[src];
        acc.x += w * v.x; acc.y += w * v.y; acc.z += w * v.z; acc.w += w * v.w;
    }
    #pragma unroll
    for (int off = 16; off; off >>= 1) {
        acc.x += __shfl_down_sync(0xffffffffu, acc.x, off);
        acc.y += __shfl_down_sync(0xffffffffu, acc.y, off);
        acc.z += __shfl_down_sync(0xffffffffu, acc.z, off);
        acc.w += __shfl_down_sync(0xffffffffu, acc.w, off);
    }
    if (lane == 0) {
        float di = g_dinv[warp];
        float4 sv = xv[warp];
        float wi = di * di;
        float4 o;
        o.x = acc.x * di + sv.x * wi;
        o.y = acc.y * di + sv.y * wi;
        o.z = acc.z * di + sv.z * wi;
        o.w = acc.w * di + sv.w * wi;
        ((float4*)g_xa)[warp] = o;
    }
}

// -------- layer-1 GEMM: xa[N,4]@W1 + b1, relu, prescale -> g_q0 fp8 --------
__global__ void gemm1_k(const float* __restrict__ W1, const float* __restrict__ b1) {
    int idx = blockIdx.x * blockDim.x + threadIdx.x;   // NN*32
    if (idx >= NN * 32) return;
    int node = idx >> 5, jc = idx & 31;
    int j = jc * 4;
    float4 a = ((const float4*)g_xa)[node];
    float d = g_dinv[node];
    float o[4];
    #pragma unroll
    for (int u = 0; u < 4; u++) {
        float acc = b1[j + u] + a.x * W1[j + u] + a.y * W1[128 + j + u]
                  + a.z * W1[256 + j + u] + a.w * W1[384 + j + u];
        o[u] = fmaxf(acc, 0.f) * d;
    }
    unsigned short lo = __nv_cvt_float2_to_fp8x2(make_float2(o[0], o[1]), __NV_SATFINITE, __NV_E4M3);
    unsigned short hi = __nv_cvt_float2_to_fp8x2(make_float2(o[2], o[3]), __NV_SATFINITE, __NV_E4M3);
    ((unsigned*)g_q0)[node * 32 + jc] = (unsigned)lo | ((unsigned)hi << 16);
}

// -------- fused GCN layer: fp8 gather -> smem fp16 A-tile, HMMA w/ gmem B-frags ----
// 64 nodes/block, 256 threads, smem = A-tile only (17.4 KB) -> 8 blocks/SM.
// outmode: 0 -> g_q0 (fp8), 1 -> g_q1 (fp8), 2 -> g_hF (fp16).
__global__ __launch_bounds__(256) void layer_k(
    int insel, int wsel, const float* __restrict__ b, int outmode, int prescale) {
    extern __shared__ char dsm[];
    __half* Is = (__half*)dsm;                  // 64*136*2 = 17408 B
    int t = threadIdx.x, lane = t & 31, wrp = t >> 5;
    int nodeBase = blockIdx.x * 64;
    const unsigned* q = qsel(insel);

    // ---- gather phase: warp per node, lane covers 4 features (4B fp8) ----
    #pragma unroll 1
    for (int r = 0; r < 8; r++) {
        int row = wrp * 8 + r;
        int n = nodeBase + row;
        if (n < NN) {
            int s = g_rowptr[n], e = g_rowptr[n + 1];
            float4 acc = q4_to_f4(q[n * 32 + lane]);   // self-loop term
            for (int p = s; p < e; p++) {
                int src = __ldg(&g_col[p]);
                float4 f = q4_to_f4(q[src * 32 + lane]);
                acc.x += f.x; acc.y += f.y; acc.z += f.z; acc.w += f.w;
            }
            float d = g_dinv[n];
            __half2 p0 = __floats2half2_rn(acc.x * d, acc.y * d);
            __half2 p1 = __floats2half2_rn(acc.z * d, acc.w * d);
            uint2 st;
            st.x = *(unsigned*)&p0;
            st.y = *(unsigned*)&p1;
            ((uint2*)(Is + row * LDI))[lane] = st;
        } else {
            ((uint2*)(Is + row * LDI))[lane] = make_uint2(0u, 0u);
        }
    }
    __syncthreads();

    // ---- GEMM: Is[64,128] @ W via mma.m16n8k16, B-fragments streamed from gmem/L1 ----
    int mtile = wrp & 3;
    int nhalf = wrp >> 2;
    unsigned a_base = (unsigned)__cvta_generic_to_shared(
        Is + (mtile * 16 + (lane & 15)) * LDI + (lane >> 4) * 8);
    const uint2* Wf = g_Wf + wsel * 4096 + (nhalf * 8) * 32 + lane;

    float acc[8][4];
    #pragma unroll
    for (int i = 0; i < 8; i++)
        #pragma unroll
        for (int j = 0; j < 4; j++) acc[i][j] = 0.f;

    #pragma unroll
    for (int k = 0; k < 8; k++) {
        unsigned a0, a1, a2, a3;
        ldsm_x4(a0, a1, a2, a3, a_base + k * 32);
        const uint2* wk = Wf + k * 16 * 32;
        #pragma unroll
        for (int n8 = 0; n8 < 8; n8++) {
            uint2 v = __ldg(&wk[n8 * 32]);
            mma16816(acc[n8], a0, a1, a2, a3, v.x, v.y);
        }
    }

    // ---- epilogue: bias, relu, (prescale, fp8) or fp16 store ----
    int mr = lane >> 2;
    int nc = (lane & 3) * 2;
    int node0 = nodeBase + mtile * 16 + mr;
    int node1 = node0 + 8;
    bool v0 = node0 < NN, v1 = node1 < NN;
    float d0 = 1.f, d1 = 1.f;
    if (prescale) {
        if (v0) d0 = g_dinv[node0];
        if (v1) d1 = g_dinv[node1];
    }
    unsigned short* qout = (unsigned short*)(outmode ? g_q1 : g_q0);
    #pragma unroll
    for (int n8 = 0; n8 < 8; n8++) {
        int n = nhalf * 64 + n8 * 8 + nc;
        float2 bb = *(const float2*)&b[n];
        float o00 = fmaxf(acc[n8][0] + bb.x, 0.f) * d0;
        float o01 = fmaxf(acc[n8][1] + bb.y, 0.f) * d0;
        float o10 = fmaxf(acc[n8][2] + bb.x, 0.f) * d1;
        float o11 = fmaxf(acc[n8][3] + bb.y, 0.f) * d1;
        if (outmode == 2) {
            if (v0) *(__half2*)(g_hF + node0 * HH + n) = __floats2half2_rn(o00, o01);
            if (v1) *(__half2*)(g_hF + node1 * HH + n) = __floats2half2_rn(o10, o11);
        } else {
            if (v0) qout[(node0 * HH + n) >> 1] =
                __nv_cvt_float2_to_fp8x2(make_float2(o00, o01), __NV_SATFINITE, __NV_E4M3);
            if (v1) qout[(node1 * HH + n) >> 1] =
                __nv_cvt_float2_to_fp8x2(make_float2(o10, o11), __NV_SATFINITE, __NV_E4M3);
        }
    }
}

// -------- global mean pool: segment-accumulate (batch sorted), reads g_hF --------
__global__ void pool_k(const int* __restrict__ wbatch) {
    int warp = (blockIdx.x * blockDim.x + threadIdx.x) >> 5;
    int lane = threadIdx.x & 31;
    int base = warp * 16;
    if (base >= NN) return;
    int sh = g_shift;
    const uint2* hv = (const uint2*)g_hF;
    int end = base + 16; if (end > NN) end = NN;
    float4 acc = make_float4(0.f, 0.f, 0.f, 0.f);
    int cur = wbatch[base << sh];
    int cnt = 0;
    for (int n = base; n < end; n++) {
        int g = wbatch[n << sh];
        if (g != cur) {
            float* bp = &g_pooled[cur * HH + lane * 4];
            atomicAdd(bp + 0, acc.x); atomicAdd(bp + 1, acc.y);
            atomicAdd(bp + 2, acc.z); atomicAdd(bp + 3, acc.w);
            if (lane == 0) atomicAdd(&g_gcnt[cur], (float)cnt);
            acc = make_float4(0.f, 0.f, 0.f, 0.f);
            cnt = 0; cur = g;
        }
        uint2 v = hv[n * 32 + lane];
        float2 lo = __half22float2(*(const __half2*)&v.x);
        float2 hi = __half22float2(*(const __half2*)&v.y);
        acc.x += lo.x; acc.y += lo.y; acc.z += hi.x; acc.w += hi.y;
        cnt++;
    }
    float* bp = &g_pooled[cur * HH + lane * 4];
    atomicAdd(bp + 0, acc.x); atomicAdd(bp + 1, acc.y);
    atomicAdd(bp + 2, acc.z); atomicAdd(bp + 3, acc.w);
    if (lane == 0) atomicAdd(&g_gcnt[cur], (float)cnt);
}

// -------- classifier head --------
__global__ void final_k(const float* __restrict__ Wl, const float* __restrict__ bl,
                        float* __restrict__ out) {
    int idx = blockIdx.x * blockDim.x + threadIdx.x;
    if (idx >= GG * CC) return;
    int g = idx / CC, c = idx % CC;
    float inv = 1.0f / fmaxf(g_gcnt[g], 1.0f);
    float acc = bl[c];
    const float* pr = &g_pooled[g * HH];
    #pragma unroll 4
    for (int k = 0; k < HH; k++) acc += pr[k] * inv * Wl[k * CC + c];
    out[idx] = 1.0f / (1.0f + expf(-acc));
}

extern "C" void kernel_launch(void* const* d_in, const int* in_sizes, int n_in,
                              void* d_out, int out_size) {
    const float* x    = (const float*)d_in[0];
    const int*   eiw  = (const int*)d_in[1];
    const int*   batw = (const int*)d_in[2];
    const float* W1 = (const float*)d_in[3];
    const float* b1 = (const float*)d_in[4];
    const float* W2 = (const float*)d_in[5];
    const float* b2 = (const float*)d_in[6];
    const float* W3 = (const float*)d_in[7];
    const float* b3 = (const float*)d_in[8];
    const float* W4 = (const float*)d_in[9];
    const float* b4 = (const float*)d_in[10];
    const float* Wl = (const float*)d_in[11];
    const float* bl = (const float*)d_in[12];
    float* out = (float*)d_out;

    const int LAYER_SMEM = 64 * LDI * 2;   // 17408 B

    // ---- dtype detect + weight convert + CSR build ----
    detect_k<<<1, 256>>>(eiw);
    zero_k<<<(NN + 255) / 256, 256>>>();
    wcvt_k<<<(3 * 4096 + 255) / 256, 256>>>(W2, W3, W4);
    count_k<<<(EE + 255) / 256, 256>>>(eiw);
    part_k<<<NBLK, 256>>>();
    scanpart_k<<<1, 128>>>();
    scan3_k<<<NBLK, SCAN_CHUNK>>>();
    fill_k<<<(EE + 255) / 256, 256>>>(eiw);

    const int WARP_BLOCKS = (NN * 32 + 255) / 256;
    const int LAYER_BLOCKS = (NN + 63) / 64;

    // ---- layer 1: aggregate x (F=4), GEMM W1 -> g_q0 (prescaled fp8) ----
    aggx_k<<<WARP_BLOCKS, 256>>>(x);
    gemm1_k<<<(NN * 32 + 255) / 256, 256>>>(W1, b1);

    // ---- layers 2-4: fused fp8 gather + HMMA (q0 -> q1 -> q0 -> hF) ----
    layer_k<<<LAYER_BLOCKS, 256, LAYER_SMEM>>>(0, 0, b2, 1, 1);
    layer_k<<<LAYER_BLOCKS, 256, LAYER_SMEM>>>(1, 1, b3, 0, 1);
    layer_k<<<LAYER_BLOCKS, 256, LAYER_SMEM>>>(0, 2, b4, 2, 0);   // last: fp16 out, no prescale

    // ---- pool + head ----
    const int POOL_BLOCKS = ((NN + 15) / 16 * 32 + 255) / 256;
    pool_k<<<POOL_BLOCKS, 256>>>(batw);
    final_k<<<(GG * CC + 255) / 256, 256>>>(Wl, bl, out);
}